// round 4
// baseline (speedup 1.0000x reference)
#include <cuda_runtime.h>
#include <cstdint>

// Problem constants
#define B_  32
#define P_  2048
#define D_  768
#define T_  3
#define H_  192
#define O_  128
#define NSPLIT 16
#define TOKS_PER_SPLIT (P_ / NSPLIT)   // 128
#define CHUNK 32
#define SCALE 0.036084391824351615f    // 1/sqrt(768)

// ---------------- device scratch (no allocations allowed) ----------------
__device__ float g_q[T_ * D_];                       // q vectors
__device__ float g_gs[T_ * D_];                      // Wk@q, pre-scaled
__device__ float g_sb[T_];                           // (q . bk) * scale
__device__ float g_pm[B_ * NSPLIT * T_];             // partial max
__device__ float g_pl[B_ * NSPLIT * T_];             // partial sum
__device__ float g_pacc[B_ * NSPLIT * T_ * D_];      // partial weighted x
__device__ float g_xbar[T_ * B_ * D_];               // attn-weighted mean of x
__device__ float g_y1[T_ * B_ * D_];
__device__ float g_y2[T_ * B_ * D_];
__device__ float g_hbuf[T_ * B_ * H_];

// ---------------- Kernel A1: q[t,e] = task_token[t] @ Wq[t] + bq ----------------
// grid (6, T), 128 threads; thread owns one e (column of Wq[t]).
__global__ void proj_q_kernel(const float* __restrict__ tt,
                              const float* __restrict__ Wq,
                              const float* __restrict__ bq) {
    int t = blockIdx.y;
    int e = blockIdx.x * 128 + threadIdx.x;
    __shared__ float tts[D_];
    for (int i = threadIdx.x; i < D_; i += 128) tts[i] = tt[t * D_ + i];
    __syncthreads();
    const float* wp = Wq + (size_t)t * D_ * D_ + e;
    float acc = 0.f;
    #pragma unroll 8
    for (int d = 0; d < D_; d++) acc += tts[d] * wp[(size_t)d * D_];
    g_q[t * D_ + e] = acc + bq[t * D_ + e];
}

// ---------------- Kernel A2: gs[t,d] = (Wk[t] @ q[t])[d] * scale ; sb[t] ----------------
// grid (6, T), 128 threads; thread owns one d (streams one Wk row, float4).
__global__ void proj_gk_kernel(const float* __restrict__ Wk,
                               const float* __restrict__ bk) {
    int t = blockIdx.y;
    int d = blockIdx.x * 128 + threadIdx.x;
    __shared__ float qs[D_];
    for (int i = threadIdx.x; i < D_; i += 128) qs[i] = g_q[t * D_ + i];
    __syncthreads();
    const float4* wp = (const float4*)(Wk + (size_t)t * D_ * D_ + (size_t)d * D_);
    float acc = 0.f;
    #pragma unroll 4
    for (int e4 = 0; e4 < D_ / 4; e4++) {
        float4 w = wp[e4];
        acc += w.x * qs[e4 * 4 + 0] + w.y * qs[e4 * 4 + 1]
             + w.z * qs[e4 * 4 + 2] + w.w * qs[e4 * 4 + 3];
    }
    g_gs[t * D_ + d] = acc * SCALE;

    if (blockIdx.x == 0) {   // this block also reduces sb = (q.bk)*scale
        float r = 0.f;
        for (int e = threadIdx.x; e < D_; e += 128) r += qs[e] * bk[t * D_ + e];
        __shared__ float red[128];
        red[threadIdx.x] = r;
        __syncthreads();
        for (int s = 64; s > 0; s >>= 1) {
            if (threadIdx.x < s) red[threadIdx.x] += red[threadIdx.x + s];
            __syncthreads();
        }
        if (threadIdx.x == 0) g_sb[t] = red[0] * SCALE;
    }
}

// ---------------- Kernel B: split online-softmax attention over x ----------------
// grid (NSPLIT, B), 256 threads. Reads x once from HBM (phase-3 re-read hits L1).
__global__ __launch_bounds__(256, 4)
void attn_split_kernel(const float* __restrict__ x,
                       const void* __restrict__ mask_raw) {
    int b = blockIdx.y, sp = blockIdx.x;
    int tid = threadIdx.x;
    int lane = tid & 31, wid = tid >> 5;

    __shared__ __align__(16) float gs_s[T_][D_];
    __shared__ float sb_s[T_];
    __shared__ float sc_s[T_][CHUNK];
    __shared__ float w_s[T_][CHUNK];
    __shared__ float fac_s[T_];
    __shared__ float m_s[T_], l_s[T_];
    __shared__ int   mask_u8_s;   // 1 if mask is byte-typed, 0 if int32

    // ---- mask dtype probe: int32 bool array => first 32 words all in {0,1}.
    // Byte mask reinterpreted as u32: P[word<=1] = 1/8 per word -> 8^-32 ~ 0.
    if (tid == 0) mask_u8_s = 0;
    __syncthreads();
    if (tid < 32) {
        unsigned v = ((const unsigned*)mask_raw)[tid];   // 128 bytes, safe either way
        if (v > 1u) atomicOr(&mask_u8_s, 1);
    }

    for (int i = tid; i < T_ * D_; i += 256) ((float*)gs_s)[i] = g_gs[i];
    if (tid < T_) { sb_s[tid] = g_sb[tid]; m_s[tid] = -1e30f; l_s[tid] = 0.f; }
    __syncthreads();
    const bool mask_is_u8 = (mask_u8_s != 0);
    const unsigned char* mb8  = (const unsigned char*)mask_raw + (size_t)b * P_;
    const int*           mb32 = (const int*)mask_raw + (size_t)b * P_;

    float acc[T_][3];
    #pragma unroll
    for (int t = 0; t < T_; t++)
        #pragma unroll
        for (int j = 0; j < 3; j++) acc[t][j] = 0.f;

    const int p0 = sp * TOKS_PER_SPLIT;
    const float* xb = x + (size_t)b * P_ * D_;

    const float4* gs0_4 = (const float4*)gs_s[0];
    const float4* gs1_4 = (const float4*)gs_s[1];
    const float4* gs2_4 = (const float4*)gs_s[2];

    for (int c = 0; c < TOKS_PER_SPLIT; c += CHUNK) {
        // ---- phase 1: scores for 32 tokens (warp owns 4 tokens), float4 loads ----
        #pragma unroll
        for (int qi = 0; qi < 4; qi++) {
            int i = wid * 4 + qi;
            int p = p0 + c + i;
            const float4* xr4 = (const float4*)(xb + (size_t)p * D_);
            float s0 = 0.f, s1 = 0.f, s2 = 0.f;
            #pragma unroll
            for (int j = 0; j < D_ / 4 / 32; j++) {     // 6 iterations
                int idx = lane + 32 * j;
                float4 xv = xr4[idx];
                float4 g0 = gs0_4[idx], g1 = gs1_4[idx], g2 = gs2_4[idx];
                s0 += xv.x * g0.x + xv.y * g0.y + xv.z * g0.z + xv.w * g0.w;
                s1 += xv.x * g1.x + xv.y * g1.y + xv.z * g1.z + xv.w * g1.w;
                s2 += xv.x * g2.x + xv.y * g2.y + xv.z * g2.z + xv.w * g2.w;
            }
            #pragma unroll
            for (int off = 16; off; off >>= 1) {
                s0 += __shfl_xor_sync(0xffffffffu, s0, off);
                s1 += __shfl_xor_sync(0xffffffffu, s1, off);
                s2 += __shfl_xor_sync(0xffffffffu, s2, off);
            }
            if (lane == 0) {
                bool mk = mask_is_u8 ? (mb8[p] != 0) : (mb32[p] != 0);
                sc_s[0][i] = mk ? -1e30f : s0 + sb_s[0];
                sc_s[1][i] = mk ? -1e30f : s1 + sb_s[1];
                sc_s[2][i] = mk ? -1e30f : s2 + sb_s[2];
            }
        }
        __syncthreads();

        // ---- phase 2: online softmax state update (3 threads) ----
        if (tid < T_) {
            int t = tid;
            float m_old = m_s[t];
            float mc = m_old;
            #pragma unroll
            for (int i = 0; i < CHUNK; i++) mc = fmaxf(mc, sc_s[t][i]);
            if (mc <= -1e29f) {
                fac_s[t] = 1.f;
                #pragma unroll
                for (int i = 0; i < CHUNK; i++) w_s[t][i] = 0.f;
            } else {
                float fac = __expf(m_old - mc);   // underflows to 0 when m_old==-1e30
                float sum = 0.f;
                #pragma unroll
                for (int i = 0; i < CHUNK; i++) {
                    float w = __expf(sc_s[t][i] - mc);
                    w_s[t][i] = w;
                    sum += w;
                }
                l_s[t] = l_s[t] * fac + sum;
                m_s[t] = mc;
                fac_s[t] = fac;
            }
        }
        __syncthreads();

        // ---- phase 3: rescale + weighted accumulation (x re-read hits L1) ----
        float f0 = fac_s[0], f1 = fac_s[1], f2 = fac_s[2];
        #pragma unroll
        for (int j = 0; j < 3; j++) {
            acc[0][j] *= f0; acc[1][j] *= f1; acc[2][j] *= f2;
        }
        #pragma unroll 4
        for (int i = 0; i < CHUNK; i++) {
            const float* xr = xb + (size_t)(p0 + c + i) * D_;
            float x0 = xr[tid], x1 = xr[tid + 256], x2 = xr[tid + 512];
            float w0 = w_s[0][i], w1 = w_s[1][i], w2 = w_s[2][i];
            acc[0][0] += w0 * x0; acc[0][1] += w0 * x1; acc[0][2] += w0 * x2;
            acc[1][0] += w1 * x0; acc[1][1] += w1 * x1; acc[1][2] += w1 * x2;
            acc[2][0] += w2 * x0; acc[2][1] += w2 * x1; acc[2][2] += w2 * x2;
        }
        // next phase-2 is protected by the __syncthreads after next phase-1
    }

    int base = (b * NSPLIT + sp) * T_;
    if (tid < T_) { g_pm[base + tid] = m_s[tid]; g_pl[base + tid] = l_s[tid]; }
    #pragma unroll
    for (int t = 0; t < T_; t++)
        #pragma unroll
        for (int j = 0; j < 3; j++)
            g_pacc[(size_t)(base + t) * D_ + tid + j * 256] = acc[t][j];
}

// ---------------- Kernel C: combine split partials -> xbar ----------------
// grid 96 (t*B+b), 256 threads.
__global__ void combine_kernel() {
    int t = blockIdx.x / B_;
    int b = blockIdx.x % B_;
    float M = -1e30f;
    #pragma unroll
    for (int i = 0; i < NSPLIT; i++)
        M = fmaxf(M, g_pm[(b * NSPLIT + i) * T_ + t]);
    float e[NSPLIT];
    float L = 0.f;
    #pragma unroll
    for (int i = 0; i < NSPLIT; i++) {
        e[i] = __expf(g_pm[(b * NSPLIT + i) * T_ + t] - M);
        L += g_pl[(b * NSPLIT + i) * T_ + t] * e[i];
    }
    float invL = 1.f / L;
    for (int d = threadIdx.x; d < D_; d += 256) {
        float s = 0.f;
        #pragma unroll
        for (int i = 0; i < NSPLIT; i++)
            s += g_pacc[(size_t)((b * NSPLIT + i) * T_ + t) * D_ + d] * e[i];
        g_xbar[(size_t)(t * B_ + b) * D_ + d] = s * invL;
    }
}

// ---------------- generic tiny GEMM body: Y[t] = act(X[t] @ W[t] + bias + resid) ----------------
// X: (T, 32, K), W: (T, K, N). grid (N/64, T), 256 threads; K multiple of 192.
__device__ __forceinline__
void gemm32_body(const float* __restrict__ X, const float* __restrict__ W,
                 const float* __restrict__ bias, const float* __restrict__ resid,
                 float* __restrict__ Y, int K, int N, int act) {
    int t = blockIdx.y;
    int tx = threadIdx.x & 63;
    int ty = threadIdx.x >> 6;              // 0..3
    int col = blockIdx.x * 64 + tx;

    __shared__ float Xs[32][192];
    float acc[8];
    #pragma unroll
    for (int r = 0; r < 8; r++) acc[r] = 0.f;

    for (int k0 = 0; k0 < K; k0 += 192) {
        for (int i = threadIdx.x; i < 32 * 192; i += 256) {
            int r = i / 192, kk = i % 192;
            Xs[r][kk] = X[(size_t)(t * 32 + r) * K + k0 + kk];
        }
        __syncthreads();
        const float* Wp = W + ((size_t)t * K + k0) * N + col;
        #pragma unroll 4
        for (int k = 0; k < 192; k++) {
            float wv = Wp[(size_t)k * N];
            #pragma unroll
            for (int r = 0; r < 8; r++) acc[r] += Xs[ty + r * 4][k] * wv;
        }
        __syncthreads();
    }

    float bv = bias[t * N + col];
    float rv = resid ? resid[t * N + col] : 0.f;
    #pragma unroll
    for (int r = 0; r < 8; r++) {
        int row = ty + r * 4;
        float v = acc[r] + bv + rv;
        if (act) v = 0.5f * v * (1.0f + erff(v * 0.70710678118654752f));  // exact gelu
        Y[(size_t)(t * 32 + row) * N + col] = v;
    }
}

// Wrappers referencing device scratch symbols directly (no host symbol-address API).
__global__ __launch_bounds__(256)
void gemm_v_kernel(const float* __restrict__ Wv, const float* __restrict__ bv) {
    gemm32_body(g_xbar, Wv, bv, nullptr, g_y1, D_, D_, 0);
}
__global__ __launch_bounds__(256)
void gemm_o_kernel(const float* __restrict__ Wo, const float* __restrict__ bo,
                   const float* __restrict__ tt) {
    gemm32_body(g_y1, Wo, bo, tt, g_y2, D_, D_, 0);
}
__global__ __launch_bounds__(256)
void gemm_h1_kernel(const float* __restrict__ h1w, const float* __restrict__ h1b) {
    gemm32_body(g_y2, h1w, h1b, nullptr, g_hbuf, D_, H_, 1);
}
__global__ __launch_bounds__(256)
void gemm_h2_kernel(const float* __restrict__ h2w, const float* __restrict__ h2b,
                    float* __restrict__ out) {
    gemm32_body(g_hbuf, h2w, h2b, nullptr, out, H_, O_, 0);
}

// ---------------- launch (kernel launches ONLY — graph-capture safe) ----------------
extern "C" void kernel_launch(void* const* d_in, const int* in_sizes, int n_in,
                              void* d_out, int out_size) {
    const float* x    = (const float*)d_in[0];
    const void*  mask = d_in[1];                    // bool widened to int32 (probed on-device)
    const float* tt   = (const float*)d_in[2];
    const float* Wq   = (const float*)d_in[3];
    const float* bq   = (const float*)d_in[4];
    const float* Wk   = (const float*)d_in[5];
    const float* bk   = (const float*)d_in[6];
    const float* Wv   = (const float*)d_in[7];
    const float* bv   = (const float*)d_in[8];
    const float* Wo   = (const float*)d_in[9];
    const float* bo   = (const float*)d_in[10];
    const float* h1w  = (const float*)d_in[11];
    const float* h1b  = (const float*)d_in[12];
    const float* h2w  = (const float*)d_in[13];
    const float* h2b  = (const float*)d_in[14];
    float*       out  = (float*)d_out;

    proj_q_kernel<<<dim3(6, T_), 128>>>(tt, Wq, bq);
    proj_gk_kernel<<<dim3(6, T_), 128>>>(Wk, bk);
    attn_split_kernel<<<dim3(NSPLIT, B_), 256>>>(x, mask);
    combine_kernel<<<T_ * B_, 256>>>();
    gemm_v_kernel<<<dim3(12, T_), 256>>>(Wv, bv);
    gemm_o_kernel<<<dim3(12, T_), 256>>>(Wo, bo, tt);
    gemm_h1_kernel<<<dim3(3, T_), 256>>>(h1w, h1b);
    gemm_h2_kernel<<<dim3(2, T_), 256>>>(h2w, h2b, out);
}

// round 5
// speedup vs baseline: 2.2341x; 2.2341x over previous
#include <cuda_runtime.h>
#include <cstdint>

// Problem constants
#define B_  32
#define P_  2048
#define D_  768
#define T_  3
#define H_  192
#define O_  128
#define NSPLIT 16
#define TOKS_PER_SPLIT (P_ / NSPLIT)   // 128
#define CHUNK 32
#define KB_  96                         // split-K block for projections
#define NKB  (D_ / KB_)                 // 8
#define SCALE 0.036084391824351615f     // 1/sqrt(768)

// ---------------- device scratch ----------------
__device__ float g_qpart[NKB * T_ * D_];
__device__ float g_gspart[NKB * T_ * D_];
__device__ float g_q[T_ * D_];
__device__ float g_gs[T_ * D_];
__device__ float g_sb[T_];
__device__ float g_pm[B_ * NSPLIT * T_];
__device__ float g_pl[B_ * NSPLIT * T_];
__device__ float g_pacc[B_ * NSPLIT * T_ * D_];
__device__ float g_xbar[T_ * B_ * D_];
__device__ float g_y1[T_ * B_ * D_];
__device__ float g_y2[T_ * B_ * D_];
__device__ float g_hbuf[T_ * B_ * H_];

// ---------------- proj_q split-K: partial q[t,e] over k-block ----------------
// grid (6, NKB, T), 128 threads.
__global__ void proj_q_part_kernel(const float* __restrict__ tt,
                                   const float* __restrict__ Wq) {
    int t = blockIdx.z, ky = blockIdx.y;
    int e = blockIdx.x * 128 + threadIdx.x;
    int k0 = ky * KB_;
    __shared__ float tts[KB_];
    if (threadIdx.x < KB_) tts[threadIdx.x] = tt[t * D_ + k0 + threadIdx.x];
    __syncthreads();
    const float* wp = Wq + (size_t)t * D_ * D_ + (size_t)k0 * D_ + e;
    float acc = 0.f;
    #pragma unroll 8
    for (int d = 0; d < KB_; d++) acc += tts[d] * wp[(size_t)d * D_];
    g_qpart[(ky * T_ + t) * D_ + e] = acc;
}

// grid (6, T), 128 threads: q = sum partials + bq
__global__ void reduce_q_kernel(const float* __restrict__ bq) {
    int t = blockIdx.y;
    int e = blockIdx.x * 128 + threadIdx.x;
    float s = bq[t * D_ + e];
    #pragma unroll
    for (int ky = 0; ky < NKB; ky++) s += g_qpart[(ky * T_ + t) * D_ + e];
    g_q[t * D_ + e] = s;
}

// ---------------- proj_gk split-K: partial gs[t,d] over e-block ----------------
// grid (6, NKB, T), 128 threads; thread streams 96 contiguous floats of one Wk row.
__global__ void proj_gk_part_kernel(const float* __restrict__ Wk) {
    int t = blockIdx.z, ky = blockIdx.y;
    int d = blockIdx.x * 128 + threadIdx.x;
    int e0 = ky * KB_;
    __shared__ float qs[KB_];
    if (threadIdx.x < KB_) qs[threadIdx.x] = g_q[t * D_ + e0 + threadIdx.x];
    __syncthreads();
    const float4* wp = (const float4*)(Wk + (size_t)t * D_ * D_ + (size_t)d * D_ + e0);
    float acc = 0.f;
    #pragma unroll
    for (int e4 = 0; e4 < KB_ / 4; e4++) {    // 24 float4 loads
        float4 w = wp[e4];
        acc += w.x * qs[e4 * 4 + 0] + w.y * qs[e4 * 4 + 1]
             + w.z * qs[e4 * 4 + 2] + w.w * qs[e4 * 4 + 3];
    }
    g_gspart[(ky * T_ + t) * D_ + d] = acc;
}

// grid (6, T), 128 threads: gs = scale * sum; block x==0 also computes sb.
__global__ void reduce_gk_kernel(const float* __restrict__ bk) {
    int t = blockIdx.y;
    int d = blockIdx.x * 128 + threadIdx.x;
    float s = 0.f;
    #pragma unroll
    for (int ky = 0; ky < NKB; ky++) s += g_gspart[(ky * T_ + t) * D_ + d];
    g_gs[t * D_ + d] = s * SCALE;

    if (blockIdx.x == 0) {
        float r = 0.f;
        for (int e = threadIdx.x; e < D_; e += 128)
            r += g_q[t * D_ + e] * bk[t * D_ + e];
        __shared__ float red[128];
        red[threadIdx.x] = r;
        __syncthreads();
        for (int st = 64; st > 0; st >>= 1) {
            if (threadIdx.x < st) red[threadIdx.x] += red[threadIdx.x + st];
            __syncthreads();
        }
        if (threadIdx.x == 0) g_sb[t] = red[0] * SCALE;
    }
}

// ---------------- Kernel B: split online-softmax attention over x ----------------
// grid (NSPLIT, B), 256 threads.
__global__ __launch_bounds__(256, 4)
void attn_split_kernel(const float* __restrict__ x,
                       const void* __restrict__ mask_raw) {
    int b = blockIdx.y, sp = blockIdx.x;
    int tid = threadIdx.x;
    int lane = tid & 31, wid = tid >> 5;

    __shared__ __align__(16) float gs_s[T_][D_];
    __shared__ float sb_s[T_];
    __shared__ float sc_s[T_][CHUNK];
    __shared__ float w_s[T_][CHUNK];
    __shared__ float fac_s[T_];
    __shared__ float m_s[T_], l_s[T_];
    __shared__ int   mask_u8_s;

    // mask dtype probe: int32 bool => first 32 words all in {0,1}.
    if (tid == 0) mask_u8_s = 0;
    __syncthreads();
    if (tid < 32) {
        unsigned v = ((const unsigned*)mask_raw)[tid];
        if (v > 1u) atomicOr(&mask_u8_s, 1);
    }

    for (int i = tid; i < T_ * D_; i += 256) ((float*)gs_s)[i] = g_gs[i];
    if (tid < T_) { sb_s[tid] = g_sb[tid]; m_s[tid] = -1e30f; l_s[tid] = 0.f; }
    __syncthreads();
    const bool mask_is_u8 = (mask_u8_s != 0);
    const unsigned char* mb8  = (const unsigned char*)mask_raw + (size_t)b * P_;
    const int*           mb32 = (const int*)mask_raw + (size_t)b * P_;

    float acc[T_][3];
    #pragma unroll
    for (int t = 0; t < T_; t++)
        #pragma unroll
        for (int j = 0; j < 3; j++) acc[t][j] = 0.f;

    const int p0 = sp * TOKS_PER_SPLIT;
    const float* xb = x + (size_t)b * P_ * D_;

    const float4* gs0_4 = (const float4*)gs_s[0];
    const float4* gs1_4 = (const float4*)gs_s[1];
    const float4* gs2_4 = (const float4*)gs_s[2];

    for (int c = 0; c < TOKS_PER_SPLIT; c += CHUNK) {
        // ---- phase 1: scores (warp owns 4 tokens), float4 loads ----
        #pragma unroll
        for (int qi = 0; qi < 4; qi++) {
            int i = wid * 4 + qi;
            int p = p0 + c + i;
            const float4* xr4 = (const float4*)(xb + (size_t)p * D_);
            float s0 = 0.f, s1 = 0.f, s2 = 0.f;
            #pragma unroll
            for (int j = 0; j < D_ / 4 / 32; j++) {
                int idx = lane + 32 * j;
                float4 xv = xr4[idx];
                float4 g0 = gs0_4[idx], g1 = gs1_4[idx], g2 = gs2_4[idx];
                s0 += xv.x * g0.x + xv.y * g0.y + xv.z * g0.z + xv.w * g0.w;
                s1 += xv.x * g1.x + xv.y * g1.y + xv.z * g1.z + xv.w * g1.w;
                s2 += xv.x * g2.x + xv.y * g2.y + xv.z * g2.z + xv.w * g2.w;
            }
            #pragma unroll
            for (int off = 16; off; off >>= 1) {
                s0 += __shfl_xor_sync(0xffffffffu, s0, off);
                s1 += __shfl_xor_sync(0xffffffffu, s1, off);
                s2 += __shfl_xor_sync(0xffffffffu, s2, off);
            }
            if (lane == 0) {
                bool mk = mask_is_u8 ? (mb8[p] != 0) : (mb32[p] != 0);
                sc_s[0][i] = mk ? -1e30f : s0 + sb_s[0];
                sc_s[1][i] = mk ? -1e30f : s1 + sb_s[1];
                sc_s[2][i] = mk ? -1e30f : s2 + sb_s[2];
            }
        }
        __syncthreads();

        // ---- phase 2: online softmax update, warp-parallel (warps 0..2) ----
        if (wid < T_) {
            int t = wid;
            float sc = sc_s[t][lane];
            float mc = sc;
            #pragma unroll
            for (int off = 16; off; off >>= 1)
                mc = fmaxf(mc, __shfl_xor_sync(0xffffffffu, mc, off));
            float m_old = m_s[t];
            float mnew = fmaxf(m_old, mc);
            if (mnew <= -1e29f) {
                w_s[t][lane] = 0.f;
                if (lane == 0) fac_s[t] = 1.f;
            } else {
                float fac = __expf(m_old - mnew);   // 0 when m_old==-1e30
                float w = __expf(sc - mnew);        // 0 for masked entries
                w_s[t][lane] = w;
                float sum = w;
                #pragma unroll
                for (int off = 16; off; off >>= 1)
                    sum += __shfl_xor_sync(0xffffffffu, sum, off);
                if (lane == 0) {
                    l_s[t] = l_s[t] * fac + sum;
                    m_s[t] = mnew;
                    fac_s[t] = fac;
                }
            }
        }
        __syncthreads();

        // ---- phase 3: rescale + weighted accumulation (x re-read hits L2) ----
        float f0 = fac_s[0], f1 = fac_s[1], f2 = fac_s[2];
        #pragma unroll
        for (int j = 0; j < 3; j++) {
            acc[0][j] *= f0; acc[1][j] *= f1; acc[2][j] *= f2;
        }
        #pragma unroll 4
        for (int i = 0; i < CHUNK; i++) {
            const float* xr = xb + (size_t)(p0 + c + i) * D_;
            float x0 = xr[tid], x1 = xr[tid + 256], x2 = xr[tid + 512];
            float w0 = w_s[0][i], w1 = w_s[1][i], w2 = w_s[2][i];
            acc[0][0] += w0 * x0; acc[0][1] += w0 * x1; acc[0][2] += w0 * x2;
            acc[1][0] += w1 * x0; acc[1][1] += w1 * x1; acc[1][2] += w1 * x2;
            acc[2][0] += w2 * x0; acc[2][1] += w2 * x1; acc[2][2] += w2 * x2;
        }
        // next phase-2 is protected by the __syncthreads after next phase-1
    }

    int base = (b * NSPLIT + sp) * T_;
    if (tid < T_) { g_pm[base + tid] = m_s[tid]; g_pl[base + tid] = l_s[tid]; }
    #pragma unroll
    for (int t = 0; t < T_; t++)
        #pragma unroll
        for (int j = 0; j < 3; j++)
            g_pacc[(size_t)(base + t) * D_ + tid + j * 256] = acc[t][j];
}

// ---------------- Kernel C: combine split partials -> xbar ----------------
// grid (T*B, 4), 192 threads; block handles 192 d's.
__global__ void combine_kernel() {
    int t = blockIdx.x / B_;
    int b = blockIdx.x % B_;
    int d = blockIdx.y * 192 + threadIdx.x;
    float M = -1e30f;
    #pragma unroll
    for (int i = 0; i < NSPLIT; i++)
        M = fmaxf(M, g_pm[(b * NSPLIT + i) * T_ + t]);
    float L = 0.f, s = 0.f;
    #pragma unroll
    for (int i = 0; i < NSPLIT; i++) {
        float e = __expf(g_pm[(b * NSPLIT + i) * T_ + t] - M);
        L += g_pl[(b * NSPLIT + i) * T_ + t] * e;
        s += g_pacc[(size_t)((b * NSPLIT + i) * T_ + t) * D_ + d] * e;
    }
    g_xbar[(size_t)(t * B_ + b) * D_ + d] = s / L;
}

// ---------------- tiny GEMM: Y[t] = act(X[t](32,K) @ W[t](K,N) + bias + resid) ----------------
// grid (N/32, T), 256 threads. BK=96 k-chunks staged in smem (both X and W).
#define GBK 96
__device__ __forceinline__
void gemm32_body(const float* __restrict__ X, const float* __restrict__ W,
                 const float* __restrict__ bias, const float* __restrict__ resid,
                 float* __restrict__ Y, int K, int N, int act) {
    int t = blockIdx.y;
    int tid = threadIdx.x;
    int tx = tid & 31;          // col in 32-wide block
    int ty = tid >> 5;          // 0..7 row group
    int nc0 = blockIdx.x * 32;

    __shared__ float Xs[32][GBK];
    __shared__ float Ws[GBK][32];
    float acc[4];
    #pragma unroll
    for (int r = 0; r < 4; r++) acc[r] = 0.f;

    for (int k0 = 0; k0 < K; k0 += GBK) {
        // stage X (32 x 96) — coalesced
        for (int i = tid; i < 32 * GBK; i += 256) {
            int r = i / GBK, kk = i % GBK;
            Xs[r][kk] = X[(size_t)(t * 32 + r) * K + k0 + kk];
        }
        // stage W (96 x 32) — coalesced 128B rows, 12 loads in flight per thread
        for (int i = tid; i < GBK * 32; i += 256) {
            int kk = i >> 5, c = i & 31;
            Ws[kk][c] = W[((size_t)t * K + k0 + kk) * N + nc0 + c];
        }
        __syncthreads();
        #pragma unroll 8
        for (int k = 0; k < GBK; k++) {
            float wv = Ws[k][tx];
            #pragma unroll
            for (int r = 0; r < 4; r++) acc[r] += Xs[ty + r * 8][k] * wv;
        }
        __syncthreads();
    }

    int col = nc0 + tx;
    float bv = bias[t * N + col];
    float rv = resid ? resid[t * N + col] : 0.f;
    #pragma unroll
    for (int r = 0; r < 4; r++) {
        int row = ty + r * 8;
        float v = acc[r] + bv + rv;
        if (act) v = 0.5f * v * (1.0f + erff(v * 0.70710678118654752f));  // exact gelu
        Y[(size_t)(t * 32 + row) * N + col] = v;
    }
}

__global__ __launch_bounds__(256)
void gemm_v_kernel(const float* __restrict__ Wv, const float* __restrict__ bv) {
    gemm32_body(g_xbar, Wv, bv, nullptr, g_y1, D_, D_, 0);
}
__global__ __launch_bounds__(256)
void gemm_o_kernel(const float* __restrict__ Wo, const float* __restrict__ bo,
                   const float* __restrict__ tt) {
    gemm32_body(g_y1, Wo, bo, tt, g_y2, D_, D_, 0);
}
__global__ __launch_bounds__(256)
void gemm_h1_kernel(const float* __restrict__ h1w, const float* __restrict__ h1b) {
    gemm32_body(g_y2, h1w, h1b, nullptr, g_hbuf, D_, H_, 1);
}
__global__ __launch_bounds__(256)
void gemm_h2_kernel(const float* __restrict__ h2w, const float* __restrict__ h2b,
                    float* __restrict__ out) {
    gemm32_body(g_hbuf, h2w, h2b, nullptr, out, H_, O_, 0);
}

// ---------------- launch (kernel launches ONLY — graph-capture safe) ----------------
extern "C" void kernel_launch(void* const* d_in, const int* in_sizes, int n_in,
                              void* d_out, int out_size) {
    const float* x    = (const float*)d_in[0];
    const void*  mask = d_in[1];
    const float* tt   = (const float*)d_in[2];
    const float* Wq   = (const float*)d_in[3];
    const float* bq   = (const float*)d_in[4];
    const float* Wk   = (const float*)d_in[5];
    const float* bk   = (const float*)d_in[6];
    const float* Wv   = (const float*)d_in[7];
    const float* bv   = (const float*)d_in[8];
    const float* Wo   = (const float*)d_in[9];
    const float* bo   = (const float*)d_in[10];
    const float* h1w  = (const float*)d_in[11];
    const float* h1b  = (const float*)d_in[12];
    const float* h2w  = (const float*)d_in[13];
    const float* h2b  = (const float*)d_in[14];
    float*       out  = (float*)d_out;

    proj_q_part_kernel<<<dim3(6, NKB, T_), 128>>>(tt, Wq);
    reduce_q_kernel<<<dim3(6, T_), 128>>>(bq);
    proj_gk_part_kernel<<<dim3(6, NKB, T_), 128>>>(Wk);
    reduce_gk_kernel<<<dim3(6, T_), 128>>>(bk);
    attn_split_kernel<<<dim3(NSPLIT, B_), 256>>>(x, mask);
    combine_kernel<<<dim3(T_ * B_, 4), 192>>>();
    gemm_v_kernel<<<dim3(24, T_), 256>>>(Wv, bv);
    gemm_o_kernel<<<dim3(24, T_), 256>>>(Wo, bo, tt);
    gemm_h1_kernel<<<dim3(6, T_), 256>>>(h1w, h1b);
    gemm_h2_kernel<<<dim3(4, T_), 256>>>(h2w, h2b, out);
}

// round 6
// speedup vs baseline: 3.0297x; 1.3561x over previous
#include <cuda_runtime.h>
#include <cstdint>

// Problem constants
#define B_  32
#define P_  2048
#define D_  768
#define T_  3
#define H_  192
#define O_  128
#define NSPLIT 16
#define TOKS_PER_SPLIT (P_ / NSPLIT)   // 128
#define CHUNK 32
#define KBQ  48                         // split-K for proj_q
#define NKBQ (D_ / KBQ)                 // 16
#define KBG  96                         // split-E for proj_gk
#define NKBG (D_ / KBG)                 // 8
#define SCALE 0.036084391824351615f     // 1/sqrt(768)

// ---------------- device scratch ----------------
__device__ float g_qpart[NKBQ * T_ * D_];
__device__ float g_gspart[NKBG * T_ * D_];
__device__ float g_pm[B_ * NSPLIT * T_];
__device__ float g_pl[B_ * NSPLIT * T_];
__device__ float g_pacc[B_ * NSPLIT * T_ * D_];
__device__ float g_xbar[T_ * B_ * D_];
__device__ float g_y1[T_ * B_ * D_];
__device__ float g_y2[T_ * B_ * D_];
__device__ float g_hbuf[T_ * B_ * H_];

// ---------------- K1: partial q[t,e] over k-block ----------------
// grid (6, NKBQ, T), 128 threads; thread owns one e, streams 48 W rows (coalesced).
__global__ void proj_q_part_kernel(const float* __restrict__ tt,
                                   const float* __restrict__ Wq) {
    int t = blockIdx.z, ky = blockIdx.y;
    int e = blockIdx.x * 128 + threadIdx.x;
    int k0 = ky * KBQ;
    __shared__ float tts[KBQ];
    if (threadIdx.x < KBQ) tts[threadIdx.x] = tt[t * D_ + k0 + threadIdx.x];
    __syncthreads();
    const float* wp = Wq + (size_t)t * D_ * D_ + (size_t)k0 * D_ + e;
    float acc = 0.f;
    #pragma unroll 12
    for (int d = 0; d < KBQ; d++) acc += tts[d] * wp[(size_t)d * D_];
    g_qpart[(ky * T_ + t) * D_ + e] = acc;
}

// ---------------- K2: fused q-reduce + partial gs over e-block ----------------
// grid (6, NKBG, T), 128 threads. Assembles the 96-wide q slice from partials,
// then each thread streams 96 contiguous floats of one Wk row (24 float4).
// NOTE: q.bk term is constant over p -> softmax-invariant -> dropped entirely.
__global__ void proj_gk_kernel(const float* __restrict__ Wk,
                               const float* __restrict__ bq) {
    int t = blockIdx.z, ky = blockIdx.y;
    int d = blockIdx.x * 128 + threadIdx.x;
    int e0 = ky * KBG;
    __shared__ float qs[KBG];
    if (threadIdx.x < KBG) {
        int e = e0 + threadIdx.x;
        float s = bq[t * D_ + e];
        #pragma unroll
        for (int kq = 0; kq < NKBQ; kq++) s += g_qpart[(kq * T_ + t) * D_ + e];
        qs[threadIdx.x] = s;
    }
    __syncthreads();
    const float4* wp = (const float4*)(Wk + (size_t)t * D_ * D_ + (size_t)d * D_ + e0);
    float acc = 0.f;
    #pragma unroll
    for (int e4 = 0; e4 < KBG / 4; e4++) {
        float4 w = wp[e4];
        acc += w.x * qs[e4 * 4 + 0] + w.y * qs[e4 * 4 + 1]
             + w.z * qs[e4 * 4 + 2] + w.w * qs[e4 * 4 + 3];
    }
    g_gspart[(ky * T_ + t) * D_ + d] = acc;   // unscaled; SCALE applied in attn
}

// ---------------- K3: split online-softmax attention over x ----------------
// grid (NSPLIT, B), 256 threads.
__global__ __launch_bounds__(256, 4)
void attn_split_kernel(const float* __restrict__ x,
                       const void* __restrict__ mask_raw) {
    int b = blockIdx.y, sp = blockIdx.x;
    int tid = threadIdx.x;
    int lane = tid & 31, wid = tid >> 5;

    __shared__ __align__(16) float gs_s[T_][D_];
    __shared__ float sc_s[T_][CHUNK];
    __shared__ float w_s[T_][CHUNK];
    __shared__ float fac_s[T_];
    __shared__ float m_s[T_], l_s[T_];
    __shared__ int   mask_u8_s;

    // mask dtype probe: int32 bool array => first 32 words all in {0,1}.
    if (tid == 0) mask_u8_s = 0;
    __syncthreads();
    if (tid < 32) {
        unsigned v = ((const unsigned*)mask_raw)[tid];
        if (v > 1u) atomicOr(&mask_u8_s, 1);
    }

    // assemble gs = SCALE * sum of partials (L2 hits)
    for (int i = tid; i < T_ * D_; i += 256) {
        float s = 0.f;
        #pragma unroll
        for (int ky = 0; ky < NKBG; ky++) s += g_gspart[ky * T_ * D_ + i];
        ((float*)gs_s)[i] = s * SCALE;
    }
    if (tid < T_) { m_s[tid] = -1e30f; l_s[tid] = 0.f; }
    __syncthreads();
    const bool mask_is_u8 = (mask_u8_s != 0);
    const unsigned char* mb8  = (const unsigned char*)mask_raw + (size_t)b * P_;
    const int*           mb32 = (const int*)mask_raw + (size_t)b * P_;

    float4 acc0 = {0,0,0,0}, acc1 = {0,0,0,0}, acc2 = {0,0,0,0};  // d=4*tid..+3 (tid<192)

    const int p0 = sp * TOKS_PER_SPLIT;
    const float* xb = x + (size_t)b * P_ * D_;

    const float4* gs0_4 = (const float4*)gs_s[0];
    const float4* gs1_4 = (const float4*)gs_s[1];
    const float4* gs2_4 = (const float4*)gs_s[2];

    for (int c = 0; c < TOKS_PER_SPLIT; c += CHUNK) {
        // ---- phase 1: warp computes 4 tokens together; gs read once per 4 tokens ----
        {
            int i0 = wid * 4;
            int p  = p0 + c + i0;
            const float4* xr0 = (const float4*)(xb + (size_t)(p + 0) * D_);
            const float4* xr1 = (const float4*)(xb + (size_t)(p + 1) * D_);
            const float4* xr2 = (const float4*)(xb + (size_t)(p + 2) * D_);
            const float4* xr3 = (const float4*)(xb + (size_t)(p + 3) * D_);
            float s[4][3];
            #pragma unroll
            for (int q = 0; q < 4; q++) { s[q][0] = 0.f; s[q][1] = 0.f; s[q][2] = 0.f; }
            #pragma unroll
            for (int j = 0; j < D_ / 128; j++) {          // 6 iterations
                int idx = lane + 32 * j;
                float4 g0 = gs0_4[idx], g1 = gs1_4[idx], g2 = gs2_4[idx];
                float4 xv0 = xr0[idx], xv1 = xr1[idx], xv2 = xr2[idx], xv3 = xr3[idx];
                s[0][0] += xv0.x*g0.x + xv0.y*g0.y + xv0.z*g0.z + xv0.w*g0.w;
                s[0][1] += xv0.x*g1.x + xv0.y*g1.y + xv0.z*g1.z + xv0.w*g1.w;
                s[0][2] += xv0.x*g2.x + xv0.y*g2.y + xv0.z*g2.z + xv0.w*g2.w;
                s[1][0] += xv1.x*g0.x + xv1.y*g0.y + xv1.z*g0.z + xv1.w*g0.w;
                s[1][1] += xv1.x*g1.x + xv1.y*g1.y + xv1.z*g1.z + xv1.w*g1.w;
                s[1][2] += xv1.x*g2.x + xv1.y*g2.y + xv1.z*g2.z + xv1.w*g2.w;
                s[2][0] += xv2.x*g0.x + xv2.y*g0.y + xv2.z*g0.z + xv2.w*g0.w;
                s[2][1] += xv2.x*g1.x + xv2.y*g1.y + xv2.z*g1.z + xv2.w*g1.w;
                s[2][2] += xv2.x*g2.x + xv2.y*g2.y + xv2.z*g2.z + xv2.w*g2.w;
                s[3][0] += xv3.x*g0.x + xv3.y*g0.y + xv3.z*g0.z + xv3.w*g0.w;
                s[3][1] += xv3.x*g1.x + xv3.y*g1.y + xv3.z*g1.z + xv3.w*g1.w;
                s[3][2] += xv3.x*g2.x + xv3.y*g2.y + xv3.z*g2.z + xv3.w*g2.w;
            }
            #pragma unroll
            for (int off = 16; off; off >>= 1)
                #pragma unroll
                for (int q = 0; q < 4; q++) {
                    s[q][0] += __shfl_xor_sync(0xffffffffu, s[q][0], off);
                    s[q][1] += __shfl_xor_sync(0xffffffffu, s[q][1], off);
                    s[q][2] += __shfl_xor_sync(0xffffffffu, s[q][2], off);
                }
            if (lane == 0) {
                #pragma unroll
                for (int q = 0; q < 4; q++) {
                    bool mk = mask_is_u8 ? (mb8[p + q] != 0) : (mb32[p + q] != 0);
                    sc_s[0][i0 + q] = mk ? -1e30f : s[q][0];
                    sc_s[1][i0 + q] = mk ? -1e30f : s[q][1];
                    sc_s[2][i0 + q] = mk ? -1e30f : s[q][2];
                }
            }
        }
        __syncthreads();

        // ---- phase 2: online softmax update, warp-parallel (warps 0..2) ----
        if (wid < T_) {
            int t = wid;
            float sc = sc_s[t][lane];
            float mc = sc;
            #pragma unroll
            for (int off = 16; off; off >>= 1)
                mc = fmaxf(mc, __shfl_xor_sync(0xffffffffu, mc, off));
            float m_old = m_s[t];
            float mnew = fmaxf(m_old, mc);
            if (mnew <= -1e29f) {
                w_s[t][lane] = 0.f;
                if (lane == 0) fac_s[t] = 1.f;
            } else {
                float fac = __expf(m_old - mnew);   // 0 when m_old==-1e30
                float w = __expf(sc - mnew);        // 0 for masked entries
                w_s[t][lane] = w;
                float sum = w;
                #pragma unroll
                for (int off = 16; off; off >>= 1)
                    sum += __shfl_xor_sync(0xffffffffu, sum, off);
                if (lane == 0) {
                    l_s[t] = l_s[t] * fac + sum;
                    m_s[t] = mnew;
                    fac_s[t] = fac;
                }
            }
        }
        __syncthreads();

        // ---- phase 3: rescale + weighted accumulation in float4 (192 threads) ----
        if (tid < D_ / 4) {
            float f0 = fac_s[0], f1 = fac_s[1], f2 = fac_s[2];
            acc0.x *= f0; acc0.y *= f0; acc0.z *= f0; acc0.w *= f0;
            acc1.x *= f1; acc1.y *= f1; acc1.z *= f1; acc1.w *= f1;
            acc2.x *= f2; acc2.y *= f2; acc2.z *= f2; acc2.w *= f2;
            #pragma unroll 4
            for (int i = 0; i < CHUNK; i++) {
                float4 xv = ((const float4*)(xb + (size_t)(p0 + c + i) * D_))[tid];
                float w0 = w_s[0][i], w1 = w_s[1][i], w2 = w_s[2][i];
                acc0.x += w0*xv.x; acc0.y += w0*xv.y; acc0.z += w0*xv.z; acc0.w += w0*xv.w;
                acc1.x += w1*xv.x; acc1.y += w1*xv.y; acc1.z += w1*xv.z; acc1.w += w1*xv.w;
                acc2.x += w2*xv.x; acc2.y += w2*xv.y; acc2.z += w2*xv.z; acc2.w += w2*xv.w;
            }
        }
        __syncthreads();   // protect w_s/fac_s before next chunk's phase 2
    }

    int base = (b * NSPLIT + sp) * T_;
    if (tid < T_) { g_pm[base + tid] = m_s[tid]; g_pl[base + tid] = l_s[tid]; }
    if (tid < D_ / 4) {
        ((float4*)&g_pacc[(size_t)(base + 0) * D_])[tid] = acc0;
        ((float4*)&g_pacc[(size_t)(base + 1) * D_])[tid] = acc1;
        ((float4*)&g_pacc[(size_t)(base + 2) * D_])[tid] = acc2;
    }
}

// ---------------- K4: combine split partials -> xbar ----------------
// grid (T*B, 4), 192 threads.
__global__ void combine_kernel() {
    int t = blockIdx.x / B_;
    int b = blockIdx.x % B_;
    int d = blockIdx.y * 192 + threadIdx.x;
    float M = -1e30f;
    #pragma unroll
    for (int i = 0; i < NSPLIT; i++)
        M = fmaxf(M, g_pm[(b * NSPLIT + i) * T_ + t]);
    float L = 0.f, s = 0.f;
    #pragma unroll
    for (int i = 0; i < NSPLIT; i++) {
        float e = __expf(g_pm[(b * NSPLIT + i) * T_ + t] - M);
        L += g_pl[(b * NSPLIT + i) * T_ + t] * e;
        s += g_pacc[(size_t)((b * NSPLIT + i) * T_ + t) * D_ + d] * e;
    }
    g_xbar[(size_t)(t * B_ + b) * D_ + d] = s / L;
}

// ---------------- tiny GEMM: Y[t] = act(X[t](32,K) @ W[t](K,N) + bias + resid) ----------------
// grid (N/32, T), 256 threads; float4-staged smem tiles.
#define GBK 96
__device__ __forceinline__
void gemm32_body(const float* __restrict__ X, const float* __restrict__ W,
                 const float* __restrict__ bias, const float* __restrict__ resid,
                 float* __restrict__ Y, int K, int N, int act) {
    int t = blockIdx.y;
    int tid = threadIdx.x;
    int tx = tid & 31;
    int ty = tid >> 5;              // 0..7
    int nc0 = blockIdx.x * 32;

    __shared__ __align__(16) float Xs[32][GBK];
    __shared__ __align__(16) float Ws[GBK][32];
    float acc[4] = {0.f, 0.f, 0.f, 0.f};

    for (int k0 = 0; k0 < K; k0 += GBK) {
        // stage X (32 x 96) as float4: 768 float4 / 256 thr = 3 each
        for (int i = tid; i < 32 * (GBK / 4); i += 256) {
            int r = i / (GBK / 4), c4 = i % (GBK / 4);
            float4 v = ((const float4*)(X + (size_t)(t * 32 + r) * K + k0))[c4];
            ((float4*)Xs[r])[c4] = v;
        }
        // stage W (96 x 32) as float4: 96 rows x 8 float4 = 768 / 256 = 3 each
        for (int i = tid; i < GBK * 8; i += 256) {
            int kk = i >> 3, c4 = i & 7;
            float4 v = ((const float4*)(W + ((size_t)t * K + k0 + kk) * N + nc0))[c4];
            ((float4*)Ws[kk])[c4] = v;
        }
        __syncthreads();
        #pragma unroll 8
        for (int k = 0; k < GBK; k++) {
            float wv = Ws[k][tx];
            #pragma unroll
            for (int r = 0; r < 4; r++) acc[r] += Xs[ty + r * 8][k] * wv;
        }
        __syncthreads();
    }

    int col = nc0 + tx;
    float bv = bias[t * N + col];
    float rv = resid ? resid[t * N + col] : 0.f;
    #pragma unroll
    for (int r = 0; r < 4; r++) {
        int row = ty + r * 8;
        float v = acc[r] + bv + rv;
        if (act) v = 0.5f * v * (1.0f + erff(v * 0.70710678118654752f));  // exact gelu
        Y[(size_t)(t * 32 + row) * N + col] = v;
    }
}

__global__ __launch_bounds__(256)
void gemm_v_kernel(const float* __restrict__ Wv, const float* __restrict__ bv) {
    gemm32_body(g_xbar, Wv, bv, nullptr, g_y1, D_, D_, 0);
}
__global__ __launch_bounds__(256)
void gemm_o_kernel(const float* __restrict__ Wo, const float* __restrict__ bo,
                   const float* __restrict__ tt) {
    gemm32_body(g_y1, Wo, bo, tt, g_y2, D_, D_, 0);
}
__global__ __launch_bounds__(256)
void gemm_h1_kernel(const float* __restrict__ h1w, const float* __restrict__ h1b) {
    gemm32_body(g_y2, h1w, h1b, nullptr, g_hbuf, D_, H_, 1);
}
__global__ __launch_bounds__(256)
void gemm_h2_kernel(const float* __restrict__ h2w, const float* __restrict__ h2b,
                    float* __restrict__ out) {
    gemm32_body(g_hbuf, h2w, h2b, nullptr, out, H_, O_, 0);
}

// ---------------- launch (kernel launches ONLY — graph-capture safe) ----------------
extern "C" void kernel_launch(void* const* d_in, const int* in_sizes, int n_in,
                              void* d_out, int out_size) {
    const float* x    = (const float*)d_in[0];
    const void*  mask = d_in[1];
    const float* tt   = (const float*)d_in[2];
    const float* Wq   = (const float*)d_in[3];
    const float* bq   = (const float*)d_in[4];
    const float* Wk   = (const float*)d_in[5];
    // d_in[6] = bk: dropped (softmax-invariant)
    const float* Wv   = (const float*)d_in[7];
    const float* bv   = (const float*)d_in[8];
    const float* Wo   = (const float*)d_in[9];
    const float* bo   = (const float*)d_in[10];
    const float* h1w  = (const float*)d_in[11];
    const float* h1b  = (const float*)d_in[12];
    const float* h2w  = (const float*)d_in[13];
    const float* h2b  = (const float*)d_in[14];
    float*       out  = (float*)d_out;

    proj_q_part_kernel<<<dim3(6, NKBQ, T_), 128>>>(tt, Wq);
    proj_gk_kernel<<<dim3(6, NKBG, T_), 128>>>(Wk, bq);
    attn_split_kernel<<<dim3(NSPLIT, B_), 256>>>(x, mask);
    combine_kernel<<<dim3(T_ * B_, 4), 192>>>();
    gemm_v_kernel<<<dim3(24, T_), 256>>>(Wv, bv);
    gemm_o_kernel<<<dim3(24, T_), 256>>>(Wo, bo, tt);
    gemm_h1_kernel<<<dim3(6, T_), 256>>>(h1w, h1b);
    gemm_h2_kernel<<<dim3(4, T_), 256>>>(h2w, h2b, out);
}